// round 2
// baseline (speedup 1.0000x reference)
#include <cuda_runtime.h>
#include <cstdint>

// Problem constants (fixed shapes)
#define BATCH   2
#define NLIGHT  8
#define HDIM    128
#define D0      128
#define D1      128
#define D2      128
#define NCAM    3
#define NNZ     2097152              // 2^21
#define XYZ     (D0*D1*D2)           // 2^21
#define ROWS_T  (D0*D1)              // 16384
#define BN      (BATCH*NLIGHT)       // 16
#define OUTSZ   (BATCH*NLIGHT*NCAM*D0*D1)  // 786432

// exponnorm params
#define P_K     1.790987517302874f
#define P_LOC   -0.08208043639065216f
#define P_SCALE 0.05720079131427573f

// ---------------- device scratch (static, no allocations) ----------------
__device__ float  g_w[NLIGHT*HDIM];          // normalized sigmoid weights (N,H)
__device__ float  g_light8[ROWS_T*NLIGHT];   // light[n, x, z] packed [xz][n], 512KB
__device__ float2 g_d2[XYZ];                 // density transposed [col](b0,b1), 16MB
__device__ float  g_acc[NCAM*ROWS_T*BN];     // accumulator [c][row][bn], 3MB

// ---------------- threefry2x32 ----------------
__host__ __device__ __forceinline__ unsigned rotl32(unsigned x, int r) {
    return (x << r) | (x >> (32 - r));
}

__host__ __device__ __forceinline__ void threefry2x32(
    unsigned k0, unsigned k1, unsigned x0, unsigned x1,
    unsigned* o0, unsigned* o1)
{
    unsigned ks0 = k0, ks1 = k1, ks2 = k0 ^ k1 ^ 0x1BD11BDAu;
    x0 += ks0; x1 += ks1;
#define TF_R4(a,b,c,d) \
    x0 += x1; x1 = rotl32(x1,a); x1 ^= x0; \
    x0 += x1; x1 = rotl32(x1,b); x1 ^= x0; \
    x0 += x1; x1 = rotl32(x1,c); x1 ^= x0; \
    x0 += x1; x1 = rotl32(x1,d); x1 ^= x0;
    TF_R4(13,15,26,6);  x0 += ks1; x1 += ks2 + 1u;
    TF_R4(17,29,16,24); x0 += ks2; x1 += ks0 + 2u;
    TF_R4(13,15,26,6);  x0 += ks0; x1 += ks1 + 3u;
    TF_R4(17,29,16,24); x0 += ks1; x1 += ks2 + 4u;
    TF_R4(13,15,26,6);  x0 += ks2; x1 += ks0 + 5u;
#undef TF_R4
    *o0 = x0; *o1 = x1;
}

// Partitionable threefry random_bits (jax_threefry_partitionable=True, the
// modern JAX default): element i uses 64-bit counter i -> (hi=0, lo=i),
// 32-bit result = out0 ^ out1.
__device__ __forceinline__ unsigned tf_bits_part(unsigned k0, unsigned k1, unsigned i) {
    unsigned o0, o1;
    threefry2x32(k0, k1, 0u, i, &o0, &o1);
    return o0 ^ o1;
}

// ---------------- kernels ----------------

// 1 block, 1024 threads: w = sigmoid(lp) / ||sigmoid(lp)||_F
__global__ void k_lightnorm(const float* __restrict__ lp) {
    __shared__ float red[32];
    int t = threadIdx.x;
    float s = 1.0f / (1.0f + expf(-lp[t]));
    float v = s * s;
    #pragma unroll
    for (int off = 16; off > 0; off >>= 1)
        v += __shfl_xor_sync(0xFFFFFFFFu, v, off);
    if ((t & 31) == 0) red[t >> 5] = v;
    __syncthreads();
    if (t < 32) {
        float w = red[t];
        #pragma unroll
        for (int off = 16; off > 0; off >>= 1)
            w += __shfl_xor_sync(0xFFFFFFFFu, w, off);
        if (t == 0) red[0] = sqrtf(w);
    }
    __syncthreads();
    g_w[t] = s / red[0];
}

// light8[xz][n] = sum_h light_info[h][xz] * w[n][h]
__global__ void __launch_bounds__(256) k_light8(const float* __restrict__ li) {
    __shared__ float w[NLIGHT*HDIM];
    for (int i = threadIdx.x; i < NLIGHT*HDIM; i += 256) w[i] = g_w[i];
    __syncthreads();
    int xz = blockIdx.x * 256 + threadIdx.x;
    float acc[NLIGHT];
    #pragma unroll
    for (int n = 0; n < NLIGHT; n++) acc[n] = 0.0f;
    #pragma unroll 4
    for (int h = 0; h < HDIM; h++) {
        float v = li[h * ROWS_T + xz];
        #pragma unroll
        for (int n = 0; n < NLIGHT; n++)
            acc[n] = fmaf(v, w[n * HDIM + h], acc[n]);
    }
    #pragma unroll
    for (int n = 0; n < NLIGHT; n++)
        g_light8[xz * NLIGHT + n] = acc[n];
}

// density transpose: d2[col] = (dv[0][col], dv[1][col])
__global__ void __launch_bounds__(256) k_d2(const float* __restrict__ dv) {
    int i = blockIdx.x * 256 + threadIdx.x;
    g_d2[i] = make_float2(dv[i], dv[XYZ + i]);
}

// zero accumulator (float4)
__global__ void __launch_bounds__(256) k_zero() {
    int i = blockIdx.x * 256 + threadIdx.x;
    reinterpret_cast<float4*>(g_acc)[i] = make_float4(0.f, 0.f, 0.f, 0.f);
}

__device__ __forceinline__ void red_v4(float* p, float a, float b, float c, float d) {
    unsigned long long gp = __cvta_generic_to_global((void*)p);
    asm volatile("red.global.add.v4.f32 [%0], {%1,%2,%3,%4};"
                 :: "l"(gp), "f"(a), "f"(b), "f"(c), "f"(d) : "memory");
}

// scatter: one thread per (camera, nnz)
__global__ void __launch_bounds__(256) k_scatter(
    const int* __restrict__ rows, const int* __restrict__ cols,
    const float* __restrict__ vals)
{
    int idx = blockIdx.x * 256 + threadIdx.x;   // 0 .. 3*NNZ-1
    int c   = idx >> 21;                        // camera
    int r   = rows[idx];
    int col = cols[idx];
    float v = vals[idx];

    float2 d = g_d2[col];
    int xz = ((col >> 14) << 7) | (col & 127);
    const float4* lp = reinterpret_cast<const float4*>(g_light8 + (xz << 3));
    float4 l0 = lp[0];
    float4 l1 = lp[1];

    float a = v * d.x;
    float b = v * d.y;

    float* base = g_acc + ((((unsigned)c << 14) + (unsigned)r) << 4);
    red_v4(base + 0,  a*l0.x, a*l0.y, a*l0.z, a*l0.w);
    red_v4(base + 4,  a*l1.x, a*l1.y, a*l1.z, a*l1.w);
    red_v4(base + 8,  b*l0.x, b*l0.y, b*l0.z, b*l0.w);
    red_v4(base + 12, b*l1.x, b*l1.y, b*l1.z, b*l1.w);
}

// finalize: out[b,n,c,X,Y] = acc[c][X*128+Y][b*8+n] * (1 + noise[i])
__global__ void __launch_bounds__(256) k_final(
    float* __restrict__ out,
    unsigned kn0, unsigned kn1, unsigned ke0, unsigned ke1)
{
    int i = blockIdx.x * 256 + threadIdx.x;   // 0 .. OUTSZ-1
    int r  = i & (ROWS_T - 1);
    int t  = i >> 14;          // bn*3 + c
    int bn = t / NCAM;
    int c  = t - bn * NCAM;

    float x = g_acc[((((unsigned)c << 14) + (unsigned)r) << 4) + (unsigned)bn];

    // normal(kn): uniform in [nextafter(-1,0), 1), z = sqrt(2)*erfinv(u)
    unsigned nb = tf_bits_part(kn0, kn1, (unsigned)i);
    float fn = __uint_as_float((nb >> 9) | 0x3f800000u) - 1.0f;
    const float lo = -0.99999994f;                 // nextafterf(-1,0)
    float u = fmaxf(lo, fn * (1.0f - lo) + lo);
    float nrm = 1.41421356237309515f * erfinvf(u);

    // exponential(ke): u in [0,1), e = -log1p(-u)
    unsigned eb = tf_bits_part(ke0, ke1, (unsigned)i);
    float fe = __uint_as_float((eb >> 9) | 0x3f800000u) - 1.0f;
    float ex = -log1pf(-fe);

    float noise = (P_LOC + P_SCALE * nrm) + (P_K * P_SCALE) * ex;
    out[i] = x + x * noise;
}

// ---------------- launch ----------------
extern "C" void kernel_launch(void* const* d_in, const int* in_sizes, int n_in,
                              void* d_out, int out_size)
{
    const float* density    = (const float*)d_in[0];  // (2,128,128,128)
    const float* light_pat  = (const float*)d_in[1];  // (8,128)
    const float* light_info = (const float*)d_in[2];  // (128,128,128)
    const int*   ray_rows   = (const int*)d_in[3];    // (3, NNZ)
    const int*   ray_cols   = (const int*)d_in[4];    // (3, NNZ)
    const float* ray_vals   = (const float*)d_in[5];  // (3, NNZ)
    float* out = (float*)d_out;

    // jax.random.key(42) -> key data (hi=0, lo=42).
    // Partitionable split(key, 2): subkey_i = threefry(k, hi=0, lo=i) full pair.
    unsigned kn0, kn1, ke0, ke1;
    threefry2x32(0u, 42u, 0u, 0u, &kn0, &kn1);   // subkey 0 -> normal
    threefry2x32(0u, 42u, 0u, 1u, &ke0, &ke1);   // subkey 1 -> exponential

    k_lightnorm<<<1, NLIGHT*HDIM>>>(light_pat);
    k_light8<<<ROWS_T/256, 256>>>(light_info);
    k_d2<<<XYZ/256, 256>>>(density);
    k_zero<<<(NCAM*ROWS_T*BN/4)/256, 256>>>();
    k_scatter<<<(NCAM*NNZ)/256, 256>>>(ray_rows, ray_cols, ray_vals);
    k_final<<<OUTSZ/256, 256>>>(out, kn0, kn1, ke0, ke1);
}

// round 3
// speedup vs baseline: 1.0083x; 1.0083x over previous
#include <cuda_runtime.h>
#include <cstdint>

// Problem constants (fixed shapes)
#define BATCH   2
#define NLIGHT  8
#define HDIM    128
#define D0      128
#define D1      128
#define D2      128
#define NCAM    3
#define NNZ     2097152              // 2^21
#define XYZ     (D0*D1*D2)           // 2^21
#define ROWS_T  (D0*D1)              // 16384
#define BN      (BATCH*NLIGHT)       // 16
#define OUTSZ   (BATCH*NLIGHT*NCAM*D0*D1)  // 786432

// exponnorm params
#define P_K     1.790987517302874f
#define P_LOC   -0.08208043639065216f
#define P_SCALE 0.05720079131427573f

// ---------------- device scratch (static, no allocations) ----------------
__device__ float  g_light8[ROWS_T*NLIGHT];   // light[n, x, z] packed [xz][n], 512KB
__device__ float2 g_d2[XYZ];                 // density transposed [col](b0,b1), 16MB
__device__ float  g_acc[NCAM*ROWS_T*BN];     // accumulator [c][row][bn], 3MB

// ---------------- threefry2x32 ----------------
__host__ __device__ __forceinline__ unsigned rotl32(unsigned x, int r) {
    return (x << r) | (x >> (32 - r));
}

__host__ __device__ __forceinline__ void threefry2x32(
    unsigned k0, unsigned k1, unsigned x0, unsigned x1,
    unsigned* o0, unsigned* o1)
{
    unsigned ks0 = k0, ks1 = k1, ks2 = k0 ^ k1 ^ 0x1BD11BDAu;
    x0 += ks0; x1 += ks1;
#define TF_R4(a,b,c,d) \
    x0 += x1; x1 = rotl32(x1,a); x1 ^= x0; \
    x0 += x1; x1 = rotl32(x1,b); x1 ^= x0; \
    x0 += x1; x1 = rotl32(x1,c); x1 ^= x0; \
    x0 += x1; x1 = rotl32(x1,d); x1 ^= x0;
    TF_R4(13,15,26,6);  x0 += ks1; x1 += ks2 + 1u;
    TF_R4(17,29,16,24); x0 += ks2; x1 += ks0 + 2u;
    TF_R4(13,15,26,6);  x0 += ks0; x1 += ks1 + 3u;
    TF_R4(17,29,16,24); x0 += ks1; x1 += ks2 + 4u;
    TF_R4(13,15,26,6);  x0 += ks2; x1 += ks0 + 5u;
#undef TF_R4
    *o0 = x0; *o1 = x1;
}

// Partitionable threefry random_bits: element i -> counter (0, i), out0 ^ out1.
__device__ __forceinline__ unsigned tf_bits_part(unsigned k0, unsigned k1, unsigned i) {
    unsigned o0, o1;
    threefry2x32(k0, k1, 0u, i, &o0, &o1);
    return o0 ^ o1;
}

// ---------------- kernels ----------------

// Fused: each block redundantly computes w = sigmoid(lp)/||sigmoid(lp)||,
// then computes light8 for its 256 xz positions.
// light8[xz][n] = sum_h light_info[h][xz] * w[n][h]
__global__ void __launch_bounds__(256) k_light(
    const float* __restrict__ lp, const float* __restrict__ li)
{
    __shared__ float w[NLIGHT*HDIM];
    __shared__ float red[8];
    int t = threadIdx.x;

    // sigmoid + local sum of squares (4 elems per thread)
    float sumsq = 0.0f;
    #pragma unroll
    for (int j = 0; j < 4; j++) {
        int i = t + j * 256;
        float s = 1.0f / (1.0f + expf(-lp[i]));
        w[i] = s;
        sumsq += s * s;
    }
    #pragma unroll
    for (int off = 16; off > 0; off >>= 1)
        sumsq += __shfl_xor_sync(0xFFFFFFFFu, sumsq, off);
    if ((t & 31) == 0) red[t >> 5] = sumsq;
    __syncthreads();
    float inv;
    {
        float tot = red[0];
        #pragma unroll
        for (int k = 1; k < 8; k++) tot += red[k];
        inv = rsqrtf(tot);
    }
    __syncthreads();
    #pragma unroll
    for (int j = 0; j < 4; j++) {
        int i = t + j * 256;
        w[i] *= inv;
    }
    __syncthreads();

    int xz = blockIdx.x * 256 + t;
    float acc[NLIGHT];
    #pragma unroll
    for (int n = 0; n < NLIGHT; n++) acc[n] = 0.0f;
    #pragma unroll 4
    for (int h = 0; h < HDIM; h++) {
        float v = li[h * ROWS_T + xz];
        #pragma unroll
        for (int n = 0; n < NLIGHT; n++)
            acc[n] = fmaf(v, w[n * HDIM + h], acc[n]);
    }
    #pragma unroll
    for (int n = 0; n < NLIGHT; n++)
        g_light8[xz * NLIGHT + n] = acc[n];
}

// density transpose, float4-vectorized: d2[col] = (dv[0][col], dv[1][col])
__global__ void __launch_bounds__(256) k_d2(const float* __restrict__ dv) {
    int i = (blockIdx.x * 256 + threadIdx.x) * 4;
    float4 a = *reinterpret_cast<const float4*>(dv + i);
    float4 b = *reinterpret_cast<const float4*>(dv + XYZ + i);
    float4* o = reinterpret_cast<float4*>(g_d2 + i);
    o[0] = make_float4(a.x, b.x, a.y, b.y);
    o[1] = make_float4(a.z, b.z, a.w, b.w);
}

// zero accumulator (float4)
__global__ void __launch_bounds__(256) k_zero() {
    int i = blockIdx.x * 256 + threadIdx.x;
    reinterpret_cast<float4*>(g_acc)[i] = make_float4(0.f, 0.f, 0.f, 0.f);
}

__device__ __forceinline__ void red_v4(float* p, float a, float b, float c, float d) {
    unsigned long long gp = __cvta_generic_to_global((void*)p);
    asm volatile("red.global.add.v4.f32 [%0], {%1,%2,%3,%4};"
                 :: "l"(gp), "f"(a), "f"(b), "f"(c), "f"(d) : "memory");
}

// scatter: one thread per 4 consecutive nnz (same camera; NNZ % 4 == 0)
__global__ void __launch_bounds__(256) k_scatter(
    const int* __restrict__ rows, const int* __restrict__ cols,
    const float* __restrict__ vals)
{
    int t = blockIdx.x * 256 + threadIdx.x;     // 0 .. 3*NNZ/4-1
    int cam = t >> 19;                           // NNZ/4 = 2^19 per camera

    int4   r4 = reinterpret_cast<const int4*>(rows)[t];
    int4   c4 = reinterpret_cast<const int4*>(cols)[t];
    float4 v4 = reinterpret_cast<const float4*>(vals)[t];

    int rr[4] = {r4.x, r4.y, r4.z, r4.w};
    int cc[4] = {c4.x, c4.y, c4.z, c4.w};
    float vv[4] = {v4.x, v4.y, v4.z, v4.w};

    // batched gathers for MLP
    float2 d[4];
    #pragma unroll
    for (int j = 0; j < 4; j++) d[j] = __ldg(&g_d2[cc[j]]);

    float4 l0[4], l1[4];
    #pragma unroll
    for (int j = 0; j < 4; j++) {
        int xz = ((cc[j] >> 14) << 7) | (cc[j] & 127);
        const float4* lp = reinterpret_cast<const float4*>(g_light8 + (xz << 3));
        l0[j] = __ldg(lp);
        l1[j] = __ldg(lp + 1);
    }

    float* cbase = g_acc + ((unsigned)cam << 18);   // cam * 16384 * 16
    #pragma unroll
    for (int j = 0; j < 4; j++) {
        float a = vv[j] * d[j].x;
        float b = vv[j] * d[j].y;
        float* base = cbase + ((unsigned)rr[j] << 4);
        red_v4(base + 0,  a*l0[j].x, a*l0[j].y, a*l0[j].z, a*l0[j].w);
        red_v4(base + 4,  a*l1[j].x, a*l1[j].y, a*l1[j].z, a*l1[j].w);
        red_v4(base + 8,  b*l0[j].x, b*l0[j].y, b*l0[j].z, b*l0[j].w);
        red_v4(base + 12, b*l1[j].x, b*l1[j].y, b*l1[j].z, b*l1[j].w);
    }
}

// finalize: out[b,n,c,X,Y] = acc[c][X*128+Y][b*8+n] * (1 + noise[i])
__global__ void __launch_bounds__(256) k_final(
    float* __restrict__ out,
    unsigned kn0, unsigned kn1, unsigned ke0, unsigned ke1)
{
    int i = blockIdx.x * 256 + threadIdx.x;   // 0 .. OUTSZ-1
    int r  = i & (ROWS_T - 1);
    int t  = i >> 14;          // bn*3 + c
    int bn = t / NCAM;
    int c  = t - bn * NCAM;

    float x = g_acc[((((unsigned)c << 14) + (unsigned)r) << 4) + (unsigned)bn];

    // normal(kn): uniform in [nextafter(-1,0), 1), z = sqrt(2)*erfinv(u)
    unsigned nb = tf_bits_part(kn0, kn1, (unsigned)i);
    float fn = __uint_as_float((nb >> 9) | 0x3f800000u) - 1.0f;
    const float lo = -0.99999994f;                 // nextafterf(-1,0)
    float u = fmaxf(lo, fn * (1.0f - lo) + lo);
    float nrm = 1.41421356237309515f * erfinvf(u);

    // exponential(ke): u in [0,1), e = -log1p(-u)
    unsigned eb = tf_bits_part(ke0, ke1, (unsigned)i);
    float fe = __uint_as_float((eb >> 9) | 0x3f800000u) - 1.0f;
    float ex = -log1pf(-fe);

    float noise = (P_LOC + P_SCALE * nrm) + (P_K * P_SCALE) * ex;
    out[i] = x + x * noise;
}

// ---------------- launch ----------------
extern "C" void kernel_launch(void* const* d_in, const int* in_sizes, int n_in,
                              void* d_out, int out_size)
{
    const float* density    = (const float*)d_in[0];  // (2,128,128,128)
    const float* light_pat  = (const float*)d_in[1];  // (8,128)
    const float* light_info = (const float*)d_in[2];  // (128,128,128)
    const int*   ray_rows   = (const int*)d_in[3];    // (3, NNZ)
    const int*   ray_cols   = (const int*)d_in[4];    // (3, NNZ)
    const float* ray_vals   = (const float*)d_in[5];  // (3, NNZ)
    float* out = (float*)d_out;

    // jax.random.key(42); partitionable split(key,2): subkey_i = threefry(k,(0,i))
    unsigned kn0, kn1, ke0, ke1;
    threefry2x32(0u, 42u, 0u, 0u, &kn0, &kn1);   // subkey 0 -> normal
    threefry2x32(0u, 42u, 0u, 1u, &ke0, &ke1);   // subkey 1 -> exponential

    k_light<<<ROWS_T/256, 256>>>(light_pat, light_info);
    k_d2<<<XYZ/(256*4), 256>>>(density);
    k_zero<<<(NCAM*ROWS_T*BN/4)/256, 256>>>();
    k_scatter<<<(NCAM*NNZ/4)/256, 256>>>(ray_rows, ray_cols, ray_vals);
    k_final<<<OUTSZ/256, 256>>>(out, kn0, kn1, ke0, ke1);
}